// round 7
// baseline (speedup 1.0000x reference)
#include <cuda_runtime.h>

constexpr int NB = 4;
constexpr int C  = 32;
constexpr int H  = 512;
constexpr int W  = 960;
constexpr int Ht = 128;
constexpr int Wt = 240;
constexpr int HW = H * W;
constexpr int BX = 160;     // 960 = 6*160
constexpr int UB = 2;       // channel batch

__global__ __launch_bounds__(BX)
void tile_warp_cost_kernel(const float* __restrict__ tile_plane,
                           const float* __restrict__ fea_l,
                           const float* __restrict__ fea_r,
                           float* __restrict__ out)
{
    const int x = blockIdx.x * BX + threadIdx.x;   // 0..959
    const int y = blockIdx.y;                      // 0..511
    const int b = blockIdx.z;                      // 0..3

    const int ty = y >> 2, tx = x >> 2;
    const int iy = y & 3,  jx = x & 3;

    // tile_plane [B, 3, Ht, Wt]
    const int tbase = b * 3 * Ht * Wt + ty * Wt + tx;
    const float d   = __ldg(tile_plane + tbase);
    const float ddx = __ldg(tile_plane + tbase + Ht * Wt);
    const float ddy = __ldg(tile_plane + tbase + 2 * Ht * Wt);

    // disp_d = 0 slanted-plane disparity; all 3 hypotheses share the frac weight
    const float disp0 = d + ((float)iy - 1.5f) * ddy + ((float)jx - 1.5f) * ddx;
    const float xs0   = (float)x - disp0;
    const float xf    = floorf(xs0);
    const float w     = xs0 - xf;
    const int   x00   = (int)xf;

    // taps are [x00-1 .. x00+2]; cover with aligned float2 loads
    const int  e    = (x00 - 1) & ~1;              // even 8B-aligned base
    const bool qodd = ((x00 - 1) & 1) != 0;
    const bool fastp = (e >= 0) && (e + (qodd ? 6 : 4) <= W);

    // slow path (boundary / out-of-range): exact clamped taps
    const int j0 = min(max(x00 - 1, 0), W - 1);
    const int j1 = min(max(x00,     0), W - 1);
    const int j2 = min(max(x00 + 1, 0), W - 1);
    const int j3 = min(max(x00 + 2, 0), W - 1);

    const float* pl = fea_l + (size_t)(b * C * H + y) * W + x;
    const float* pr = fea_r + (size_t)(b * C * H + y) * W;

    float cM = 0.f, c0 = 0.f, cP = 0.f, sA = 0.f;

    #pragma unroll 1
    for (int cb = 0; cb < C; cb += UB) {
        float fl[UB], t0[UB], t1[UB], t2[UB], t3[UB];

        // ---- load phase ----
        #pragma unroll
        for (int u = 0; u < UB; ++u) {
            const float* rr = pr + u * HW;
            fl[u] = __ldg(pl + u * HW);
            if (fastp) {
                const float2 v0 = __ldg((const float2*)(rr + e));
                const float2 v1 = __ldg((const float2*)(rr + e + 2));
                float2 v2 = make_float2(0.f, 0.f);
                if (qodd) v2 = __ldg((const float2*)(rr + e + 4));
                t0[u] = qodd ? v0.y : v0.x;
                t1[u] = qodd ? v1.x : v0.y;
                t2[u] = qodd ? v1.y : v1.x;
                t3[u] = qodd ? v2.x : v1.y;
            } else {
                t0[u] = __ldg(rr + j0);
                t1[u] = __ldg(rr + j1);
                t2[u] = __ldg(rr + j2);
                t3[u] = __ldg(rr + j3);
            }
        }

        // ---- compute phase ----
        #pragma unroll
        for (int u = 0; u < UB; ++u) {
            const float wP = fmaf(w, t1[u] - t0[u], t0[u]);  // disp_d = +1
            const float w0 = fmaf(w, t2[u] - t1[u], t1[u]);  // disp_d =  0
            const float wM = fmaf(w, t3[u] - t2[u], t2[u]);  // disp_d = -1
            cM += fabsf(fl[u] - wM);
            c0 += fabsf(fl[u] - w0);
            cP += fabsf(fl[u] - wP);
            sA += fabsf(fl[u]);                              // invalid-hyp fallback
        }
        pl += UB * HW;
        pr += UB * HW;
    }

    // per-pixel validity applied once at the end
    const float wm1 = (float)(W - 1);
    if (!((xs0 + 1.0f >= 0.0f) && (xs0 + 1.0f <= wm1))) cM = sA;  // disp_d = -1
    if (!((xs0        >= 0.0f) && (xs0        <= wm1))) c0 = sA;  // disp_d =  0
    if (!((xs0 - 1.0f >= 0.0f) && (xs0 - 1.0f <= wm1))) cP = sA;  // disp_d = +1

    // output [B, 48, Ht, Wt]; channel = vblock*16 + iy*4 + jx; vblocks: -1, 0, +1
    const int chsp  = (iy * 4 + jx) * (Ht * Wt);
    const int obase = b * 48 * Ht * Wt + ty * Wt + tx;
    out[obase + chsp]                = cM;
    out[obase + 16 * Ht * Wt + chsp] = c0;
    out[obase + 32 * Ht * Wt + chsp] = cP;
}

extern "C" void kernel_launch(void* const* d_in, const int* in_sizes, int n_in,
                              void* d_out, int out_size)
{
    const float* tile_plane = (const float*)d_in[0];
    const float* fea_l      = (const float*)d_in[1];
    const float* fea_r      = (const float*)d_in[2];
    float*       out        = (float*)d_out;

    dim3 grid(W / BX, H, NB);   // (6, 512, 4)
    dim3 block(BX);
    tile_warp_cost_kernel<<<grid, block>>>(tile_plane, fea_l, fea_r, out);
}

// round 8
// speedup vs baseline: 1.4255x; 1.4255x over previous
#include <cuda_runtime.h>

constexpr int NB = 4;
constexpr int C  = 32;
constexpr int H  = 512;
constexpr int W  = 960;
constexpr int Ht = 128;
constexpr int Wt = 240;
constexpr int HW = H * W;

constexpr int NT   = Wt * H * NB;   // total tile-row threads = 491520
constexpr int BLK  = 256;

__global__ __launch_bounds__(BLK)
void tile_warp_cost_kernel(const float* __restrict__ tile_plane,
                           const float* __restrict__ fea_l,
                           const float* __restrict__ fea_r,
                           float* __restrict__ out)
{
    const int g = blockIdx.x * BLK + threadIdx.x;   // flat tile-row id
    // g -> (b, y, tx)
    const int b   = g / (Wt * H);
    const int rem = g - b * (Wt * H);
    const int y   = rem / Wt;
    const int tx  = rem - y * Wt;

    const int ty = y >> 2, iy = y & 3;
    const int xb = tx << 2;                          // first pixel x of this tile row

    // tile_plane [B, 3, Ht, Wt]
    const int tbase = b * 3 * Ht * Wt + ty * Wt + tx;
    const float d   = __ldg(tile_plane + tbase);
    const float ddx = __ldg(tile_plane + tbase + Ht * Wt);
    const float ddy = __ldg(tile_plane + tbase + 2 * Ht * Wt);

    // per-pixel setup (4 pixels, jx = 0..3)
    float xs0[4], wf[4];
    int   x00[4];
    #pragma unroll
    for (int p = 0; p < 4; ++p) {
        const float disp0 = d + ((float)iy - 1.5f) * ddy + ((float)p - 1.5f) * ddx;
        xs0[p] = (float)(xb + p) - disp0;
        const float ff = floorf(xs0[p]);
        wf[p]  = xs0[p] - ff;
        x00[p] = (int)ff;
    }

    const int wbase = x00[0] - 1;                    // window start
    const int o1 = x00[1] - x00[0];
    const int o2 = x00[2] - x00[0];
    const int o3 = x00[3] - x00[0];
    const bool fastp = (wbase >= 0) && (wbase + 8 <= W) &&
                       (o1 >= 0) && (o1 <= 4) &&
                       (o2 >= 0) && (o2 <= 4) &&
                       (o3 >= 0) && (o3 <= 4);

    const float* rowL = fea_l + ((size_t)(b * C) * H + y) * W + xb;
    const float* rowR = fea_r + ((size_t)(b * C) * H + y) * W;

    float aM[4] = {0,0,0,0}, a0[4] = {0,0,0,0}, aP[4] = {0,0,0,0}, aA[4] = {0,0,0,0};

    if (fastp) {
        const float* rw = rowR + wbase;
        #pragma unroll 2
        for (int c = 0; c < C; ++c) {
            const float4 fl4 = __ldg((const float4*)(rowL + (size_t)c * HW));
            const float* rr  = rw + (size_t)c * HW;
            float wr[8];
            #pragma unroll
            for (int k = 0; k < 8; ++k) wr[k] = __ldg(rr + k);

            const float flv[4] = {fl4.x, fl4.y, fl4.z, fl4.w};
            const int   ov[4]  = {0, o1, o2, o3};

            #pragma unroll
            for (int p = 0; p < 4; ++p) {
                float t0, t1, t2, t3;
                if (p == 0) {
                    t0 = wr[0]; t1 = wr[1]; t2 = wr[2]; t3 = wr[3];
                } else {
                    const int  o  = ov[p];
                    const bool o4 = (o == 4);
                    const bool r2 = (o & 2) != 0;
                    const bool r1 = (o & 1) != 0;
                    float a[7];
                    #pragma unroll
                    for (int k = 0; k < 4; ++k) a[k] = o4 ? wr[k + 4] : wr[k];
                    a[4] = wr[4]; a[5] = wr[5]; a[6] = wr[6];
                    float bb[5];
                    #pragma unroll
                    for (int k = 0; k < 5; ++k) bb[k] = r2 ? a[k + 2] : a[k];
                    t0 = r1 ? bb[1] : bb[0];
                    t1 = r1 ? bb[2] : bb[1];
                    t2 = r1 ? bb[3] : bb[2];
                    t3 = r1 ? bb[4] : bb[3];
                }
                const float w  = wf[p];
                const float hP = fmaf(w, t1 - t0, t0);   // disp_d = +1
                const float h0 = fmaf(w, t2 - t1, t1);   // disp_d =  0
                const float hM = fmaf(w, t3 - t2, t2);   // disp_d = -1
                const float fl = flv[p];
                aM[p] += fabsf(fl - hM);
                a0[p] += fabsf(fl - h0);
                aP[p] += fabsf(fl - hP);
                aA[p] += fabsf(fl);
            }
        }
    } else {
        // exact clamped scalar-gather path (boundary / pathological slope)
        #pragma unroll 2
        for (int c = 0; c < C; ++c) {
            const float4 fl4 = __ldg((const float4*)(rowL + (size_t)c * HW));
            const float* rr  = rowR + (size_t)c * HW;
            const float flv[4] = {fl4.x, fl4.y, fl4.z, fl4.w};
            #pragma unroll
            for (int p = 0; p < 4; ++p) {
                const int xp = x00[p];
                const int j0 = min(max(xp - 1, 0), W - 1);
                const int j1 = min(max(xp,     0), W - 1);
                const int j2 = min(max(xp + 1, 0), W - 1);
                const int j3 = min(max(xp + 2, 0), W - 1);
                const float t0 = __ldg(rr + j0), t1 = __ldg(rr + j1);
                const float t2 = __ldg(rr + j2), t3 = __ldg(rr + j3);
                const float w  = wf[p];
                const float hP = fmaf(w, t1 - t0, t0);
                const float h0 = fmaf(w, t2 - t1, t1);
                const float hM = fmaf(w, t3 - t2, t2);
                const float fl = flv[p];
                aM[p] += fabsf(fl - hM);
                a0[p] += fabsf(fl - h0);
                aP[p] += fabsf(fl - hP);
                aA[p] += fabsf(fl);
            }
        }
    }

    // epilogue: validity + tile-unshuffled stores  out[B, 48, Ht, Wt]
    const float wm1  = (float)(W - 1);
    const int obase  = b * 48 * Ht * Wt + ty * Wt + tx;
    const int cplane = Ht * Wt;
    #pragma unroll
    for (int p = 0; p < 4; ++p) {
        const bool vM = (xs0[p] + 1.0f >= 0.0f) && (xs0[p] + 1.0f <= wm1);
        const bool v0 = (xs0[p]        >= 0.0f) && (xs0[p]        <= wm1);
        const bool vP = (xs0[p] - 1.0f >= 0.0f) && (xs0[p] - 1.0f <= wm1);
        const float cM = vM ? aM[p] : aA[p];
        const float c0 = v0 ? a0[p] : aA[p];
        const float cP = vP ? aP[p] : aA[p];
        const int ch = iy * 4 + p;                 // sub-tile channel
        out[obase + ch * cplane]              = cM;   // hyp -1 block
        out[obase + (16 + ch) * cplane]       = c0;   // hyp  0 block
        out[obase + (32 + ch) * cplane]       = cP;   // hyp +1 block
    }
}

extern "C" void kernel_launch(void* const* d_in, const int* in_sizes, int n_in,
                              void* d_out, int out_size)
{
    const float* tile_plane = (const float*)d_in[0];
    const float* fea_l      = (const float*)d_in[1];
    const float* fea_r      = (const float*)d_in[2];
    float*       out        = (float*)d_out;

    tile_warp_cost_kernel<<<NT / BLK, BLK>>>(tile_plane, fea_l, fea_r, out);
}